// round 4
// baseline (speedup 1.0000x reference)
#include <cuda_runtime.h>
#include <stdint.h>

#define N 384
#define NN (N * N)
#define CHUNK 4096           // K-split chunk (divides 16384 and 8192)
#define KT 16
#define TS 64

// ---------------- scratch (no allocations allowed) ----------------
__device__ float g_norms[8 * N];        // [layer*2 + side][row]
__device__ float g_partial[12 * NN];    // split-K partial dots (4+4+2+2 chunk slots)
__device__ float g_cost[5 * NN];        // 4 layer costs + combined
__device__ int   g_rowcol[5 * N];       // row -> matched col, per solve

// ---------------- row squared-norms, all layers in one launch ----------------
__global__ void norms_all_kernel(const float* __restrict__ A0, const float* __restrict__ A1,
                                 const float* __restrict__ A2, const float* __restrict__ A3,
                                 int d0, int d1, int d2, int d3)
{
    int layer = blockIdx.y;
    const float* src = (layer == 0) ? A0 : (layer == 1) ? A1 : (layer == 2) ? A2 : A3;
    int d = (layer == 0) ? d0 : (layer == 1) ? d1 : (layer == 2) ? d2 : d3;
    int side = blockIdx.x / N;
    int row  = blockIdx.x - side * N;
    const float* p = src + ((size_t)side * N + row) * d;
    int t = threadIdx.x;
    float hi = 0.f, lo = 0.f;
    int c = 0;
    for (int k = t; k < d; k += 128, c++) {
        float x = p[k];
        lo += x * x;
        if ((c & 63) == 63) { hi += lo; lo = 0.f; }
    }
    hi += lo;
    __shared__ float s[4];
    #pragma unroll
    for (int off = 16; off; off >>= 1) hi += __shfl_down_sync(0xffffffffu, hi, off);
    if ((t & 31) == 0) s[t >> 5] = hi;
    __syncthreads();
    if (t == 0) g_norms[(2 * layer + side) * N + row] = (s[0] + s[1]) + (s[2] + s[3]);
}

// ---------------- split-K partial GEMM, all layers fused in one launch ----------------
// job id -> (layer, chunk, tile). Per job: 64x64 tile over K-range [chunk*CHUNK, +CHUNK).
__global__ void __launch_bounds__(256) gemm_partial_kernel(
    const float* __restrict__ A0, const float* __restrict__ A1,
    const float* __restrict__ A2, const float* __restrict__ A3,
    int d0, int d1, int d2, int d3,
    int c1, int c2, int c3)               // cumulative job counts after layers 0,1,2
{
    int b = blockIdx.x;
    int l, rel;
    if (b < c1)      { l = 0; rel = b; }
    else if (b < c2) { l = 1; rel = b - c1; }
    else if (b < c3) { l = 2; rel = b - c2; }
    else             { l = 3; rel = b - c3; }

    const float* lat = (l == 0) ? A0 : (l == 1) ? A1 : (l == 2) ? A2 : A3;
    int d = (l == 0) ? d0 : (l == 1) ? d1 : (l == 2) ? d2 : d3;
    int S0 = d0 / CHUNK, S1 = d1 / CHUNK, S2 = d2 / CHUNK;
    int slotBase = (l == 0) ? 0 : (l == 1) ? S0 : (l == 2) ? S0 + S1 : S0 + S1 + S2;

    int chunk = rel / 36;
    int tile  = rel % 36;
    int bx = tile % 6, by = tile / 6;
    int kBase = chunk * CHUNK;

    const float* A = lat;
    const float* B = lat + (size_t)N * d;
    float* out = &g_partial[(size_t)(slotBase + chunk) * NN];

    __shared__ float As[KT][TS + 4];
    __shared__ float Bs[KT][TS + 4];

    int tid = threadIdx.x;
    int tx = tid & 15, ty = tid >> 4;
    int row0 = by * TS, col0 = bx * TS;
    int lr = tid >> 2, lk = (tid & 3) * 4;

    float acc[4][4], hi[4][4];
    #pragma unroll
    for (int i = 0; i < 4; i++)
        #pragma unroll
        for (int j = 0; j < 4; j++) { acc[i][j] = 0.f; hi[i][j] = 0.f; }

    const int nt = CHUNK / KT;   // 256
    for (int it = 0; it < nt; it++) {
        int k0 = kBase + it * KT;
        float4 a = *(const float4*)(A + (size_t)(row0 + lr) * d + k0 + lk);
        float4 b4 = *(const float4*)(B + (size_t)(col0 + lr) * d + k0 + lk);
        __syncthreads();
        As[lk + 0][lr] = a.x;  As[lk + 1][lr] = a.y;  As[lk + 2][lr] = a.z;  As[lk + 3][lr] = a.w;
        Bs[lk + 0][lr] = b4.x; Bs[lk + 1][lr] = b4.y; Bs[lk + 2][lr] = b4.z; Bs[lk + 3][lr] = b4.w;
        __syncthreads();
        #pragma unroll
        for (int kk = 0; kk < KT; kk++) {
            float4 av = *(const float4*)&As[kk][ty * 4];
            float4 bv = *(const float4*)&Bs[kk][tx * 4];
            float aa[4] = {av.x, av.y, av.z, av.w};
            float bb[4] = {bv.x, bv.y, bv.z, bv.w};
            #pragma unroll
            for (int i = 0; i < 4; i++)
                #pragma unroll
                for (int j = 0; j < 4; j++)
                    acc[i][j] += aa[i] * bb[j];
        }
        if ((it & 15) == 15) {   // fold every 256 K for two-level accuracy
            #pragma unroll
            for (int i = 0; i < 4; i++)
                #pragma unroll
                for (int j = 0; j < 4; j++) { hi[i][j] += acc[i][j]; acc[i][j] = 0.f; }
        }
    }
    #pragma unroll
    for (int i = 0; i < 4; i++)
        #pragma unroll
        for (int j = 0; j < 4; j++) hi[i][j] += acc[i][j];

    #pragma unroll
    for (int i = 0; i < 4; i++) {
        int r = row0 + ty * 4 + i;
        #pragma unroll
        for (int j = 0; j < 4; j++) {
            int c = col0 + tx * 4 + j;
            out[r * N + c] = hi[i][j];
        }
    }
}

// ---------------- combine partials -> per-layer costs + combined (deterministic) ----------------
__global__ void combine_kernel(int d0, int d1, int d2, int d3) {
    int idx = blockIdx.x * blockDim.x + threadIdx.x;
    if (idx >= NN) return;
    int r = idx / N, c = idx % N;
    int S[4] = {d0 / CHUNK, d1 / CHUNK, d2 / CHUNK, d3 / CHUNK};
    int dd[4] = {d0, d1, d2, d3};
    const float wts[4] = {1.f, 0.5f, 0.25f, 0.125f};
    float comb = 0.f;
    int base = 0;
    #pragma unroll
    for (int l = 0; l < 4; l++) {
        float dot = 0.f;
        for (int ch = 0; ch < S[l]; ch++)
            dot += g_partial[(size_t)(base + ch) * NN + idx];
        base += S[l];
        float sq = (g_norms[2 * l * N + r] - 2.0f * dot) + g_norms[(2 * l + 1) * N + c];
        float cost = fmaxf(sq, 0.0f) * (1.0f / (float)dd[l]);
        g_cost[(size_t)l * NN + idx] = cost;
        comb = (l == 0) ? cost : comb + wts[l] * cost;   // ref fp32 order
    }
    g_cost[(size_t)4 * NN + idx] = comb;
}

// ---------------- sortable-u64 encoding of double (order-preserving) ----------------
__device__ __forceinline__ unsigned long long denc(double x) {
    unsigned long long u = (unsigned long long)__double_as_longlong(x);
    return (u & 0x8000000000000000ull) ? ~u : (u | 0x8000000000000000ull);
}
__device__ __forceinline__ double ddec(unsigned long long e) {
    unsigned long long u = (e & 0x8000000000000000ull) ? (e & 0x7fffffffffffffffull) : ~e;
    return __longlong_as_double((long long)u);
}

// ---------------- LAP (JV + column-reduction init, Dijkstra, fp64) : 1 block/matrix ----------------
__global__ void __launch_bounds__(N) lap_kernel() {
    int m = blockIdx.x;
    const float* __restrict__ C = &g_cost[(size_t)m * NN];

    __shared__ double u[N], v[N];
    __shared__ int matchRow[N];        // col -> row
    __shared__ int colOfRow[N];        // row -> col (-1 free)
    __shared__ int way[N];
    __shared__ int argRow[N];
    __shared__ int freeRows[N];
    __shared__ int s_nfree;
    __shared__ unsigned long long partEnc[2][12];
    __shared__ int partIdx[2][12];

    int j = threadIdx.x;

    // --- column reduction: v[j] = min_i C[i][j], greedy assignment ---
    {
        float cmin = C[j];
        int rmin = 0;
        #pragma unroll 8
        for (int i = 1; i < N; i++) {
            float cc = C[(size_t)i * N + j];
            if (cc < cmin) { cmin = cc; rmin = i; }
        }
        v[j] = (double)cmin;
        u[j] = 0.0;
        matchRow[j] = -1;
        colOfRow[j] = -1;
        argRow[j] = rmin;
    }
    __syncthreads();
    if (j == 0) {
        for (int c = 0; c < N; c++) {
            int r = argRow[c];
            if (colOfRow[r] < 0) { colOfRow[r] = c; matchRow[c] = r; }
        }
        int nf = 0;
        for (int r = 0; r < N; r++)
            if (colOfRow[r] < 0) freeRows[nf++] = r;
        s_nfree = nf;
    }
    __syncthreads();
    int nfree = s_nfree;

    double vj = v[j];

    for (int f = 0; f < nfree; f++) {
        int i = freeRows[f];
        double D = (double)C[(size_t)i * N + j] - vj;   // u[i] == 0 for free rows
        unsigned long long Denc = denc(D);
        way[j] = -1;
        bool vis = false;
        int sink = -1;
        double mind = 0.0;
        int buf = 0;
        __syncthreads();

        for (int iter = 0; iter <= N; iter++) {
            // warp-level argmin on sortable keys (tie-break: lowest index)
            unsigned long long key = vis ? ~0ull : Denc;
            int idx = j;
            #pragma unroll
            for (int off = 16; off; off >>= 1) {
                unsigned long long ok = __shfl_down_sync(0xffffffffu, key, off);
                int oi = __shfl_down_sync(0xffffffffu, idx, off);
                if (ok < key || (ok == key && oi < idx)) { key = ok; idx = oi; }
            }
            if ((j & 31) == 0) { partEnc[buf][j >> 5] = key; partIdx[buf][j >> 5] = idx; }
            __syncthreads();

            // every thread: gather partials, prefetch all 12 candidate cost rows,
            // and redundantly compute the global argmin (no 2nd barrier needed).
            unsigned long long pv[12];
            int pi[12], ci[12];
            float cw[12];
            #pragma unroll
            for (int w = 0; w < 12; w++) { pv[w] = partEnc[buf][w]; pi[w] = partIdx[buf][w]; }
            #pragma unroll
            for (int w = 0; w < 12; w++) ci[w] = matchRow[pi[w]];
            #pragma unroll
            for (int w = 0; w < 12; w++)
                cw[w] = (ci[w] >= 0) ? C[(size_t)ci[w] * N + j] : 0.0f;

            int bw = 0;
            #pragma unroll
            for (int w = 1; w < 12; w++)
                if (pv[w] < pv[bw] || (pv[w] == pv[bw] && pi[w] < pi[bw])) bw = w;

            int j1 = pi[bw];
            int i0 = ci[bw];
            mind = ddec(pv[bw]);
            if (i0 < 0) { sink = j1; break; }
            if (j == j1) vis = true;
            if (!vis) {
                double cand = mind + (double)cw[bw] - u[i0] - vj;
                if (cand < D) { D = cand; Denc = denc(D); way[j] = j1; }
            }
            buf ^= 1;
        }

        // dual updates (sink never marked visited)
        if (vis) {
            double dd = mind - D;
            vj -= dd;
            v[j] = vj;
            u[matchRow[j]] += dd;   // distinct rows per visited col: no conflict
        }
        if (j == 0) u[i] += mind;
        __syncthreads();            // duals done BEFORE augment mutates matchRow

        if (j == 0 && sink >= 0) {
            int jj = sink;
            while (true) {
                int pj = way[jj];
                if (pj < 0) { matchRow[jj] = i; break; }
                matchRow[jj] = matchRow[pj];
                jj = pj;
            }
        }
        __syncthreads();
    }

    g_rowcol[m * N + matchRow[j]] = j;   // row -> col
}

// ---------------- finalize: hamming total + outputs ----------------
__global__ void finalize_kernel(const long long* __restrict__ ipA,
                                const long long* __restrict__ ipB,
                                float* __restrict__ out, int out_size)
{
    __shared__ int idealcol[N];
    __shared__ int cnt[4];
    __shared__ float s_total;
    int t = threadIdx.x;
    if (t < 4) cnt[t] = 0;
    __syncthreads();
    idealcol[(int)ipA[t]] = (int)ipB[t];
    __syncthreads();
    #pragma unroll
    for (int l = 0; l < 4; l++)
        if (g_rowcol[l * N + t] == idealcol[t]) atomicAdd(&cnt[l], 1);
    __syncthreads();
    if (t == 0) {
        const double w[4] = {1.0, 0.5, 0.25, 0.125};
        double tot = 0.0;
        for (int l = 0; l < 4; l++)
            tot += w[l] * ((double)(2 * N - 2 * cnt[l]) / (double)N);
        s_total = (float)tot;
    }
    __syncthreads();
    float total = s_total;
    int colind = g_rowcol[4 * N + t];

    if (out_size >= 2 * N + 1) {
        if (t == 0) out[0] = total;
        out[1 + t] = (float)t;
        out[1 + N + t] = (float)colind;
        for (int idx = 2 * N + 1 + t; idx < out_size; idx += N) out[idx] = 0.0f;
    } else if (out_size == 2 * N) {
        out[t] = (float)t;
        out[N + t] = (float)colind;
    } else if (out_size >= 1) {
        if (t == 0) out[0] = total;
        for (int idx = 1 + t; idx < out_size; idx += N) out[idx] = 0.0f;
    }
}

// ---------------- launch ----------------
extern "C" void kernel_launch(void* const* d_in, const int* in_sizes, int n_in,
                              void* d_out, int out_size)
{
    const float* lat[4];
    int dims[4];
    for (int l = 0; l < 4; l++) {
        lat[l] = (const float*)d_in[l];
        dims[l] = in_sizes[l] / (2 * N);
    }
    const long long* ipA = (const long long*)d_in[4];
    const long long* ipB = (const long long*)d_in[5];

    int S0 = dims[0] / CHUNK, S1 = dims[1] / CHUNK, S2 = dims[2] / CHUNK, S3 = dims[3] / CHUNK;
    int c1 = 36 * S0, c2 = c1 + 36 * S1, c3 = c2 + 36 * S2, c4 = c3 + 36 * S3;

    norms_all_kernel<<<dim3(2 * N, 4), 128>>>(lat[0], lat[1], lat[2], lat[3],
                                              dims[0], dims[1], dims[2], dims[3]);
    gemm_partial_kernel<<<c4, 256>>>(lat[0], lat[1], lat[2], lat[3],
                                     dims[0], dims[1], dims[2], dims[3],
                                     c1, c2, c3);
    combine_kernel<<<(NN + 255) / 256, 256>>>(dims[0], dims[1], dims[2], dims[3]);
    lap_kernel<<<5, N>>>();
    finalize_kernel<<<1, N>>>(ipA, ipB, (float*)d_out, out_size);
}

// round 5
// speedup vs baseline: 1.0005x; 1.0005x over previous
#include <cuda_runtime.h>
#include <stdint.h>

#define N 384
#define NN (N * N)
#define CHUNK 4096           // K-split chunk (divides 16384 and 8192)
#define KT 16
#define TS 64

// ---------------- scratch (no allocations allowed) ----------------
__device__ float g_norms[8 * N];        // [layer*2 + side][row]
__device__ float g_partial[12 * NN];    // split-K partial dots (4+4+2+2 chunk slots)
__device__ float g_cost[5 * NN];        // 4 layer costs + combined
__device__ int   g_rowcol[5 * N];       // row -> matched col, per solve

// ---------------- row squared-norms, all layers in one launch ----------------
__global__ void norms_all_kernel(const float* __restrict__ A0, const float* __restrict__ A1,
                                 const float* __restrict__ A2, const float* __restrict__ A3,
                                 int d0, int d1, int d2, int d3)
{
    int layer = blockIdx.y;
    const float* src = (layer == 0) ? A0 : (layer == 1) ? A1 : (layer == 2) ? A2 : A3;
    int d = (layer == 0) ? d0 : (layer == 1) ? d1 : (layer == 2) ? d2 : d3;
    int side = blockIdx.x / N;
    int row  = blockIdx.x - side * N;
    const float* p = src + ((size_t)side * N + row) * d;
    int t = threadIdx.x;
    float hi = 0.f, lo = 0.f;
    int c = 0;
    for (int k = t; k < d; k += 128, c++) {
        float x = p[k];
        lo += x * x;
        if ((c & 63) == 63) { hi += lo; lo = 0.f; }
    }
    hi += lo;
    __shared__ float s[4];
    #pragma unroll
    for (int off = 16; off; off >>= 1) hi += __shfl_down_sync(0xffffffffu, hi, off);
    if ((t & 31) == 0) s[t >> 5] = hi;
    __syncthreads();
    if (t == 0) g_norms[(2 * layer + side) * N + row] = (s[0] + s[1]) + (s[2] + s[3]);
}

// ---------------- split-K partial GEMM, all layers fused in one launch ----------------
// job id -> (layer, chunk, tile). Per job: 64x64 tile over K-range [chunk*CHUNK, +CHUNK).
__global__ void __launch_bounds__(256) gemm_partial_kernel(
    const float* __restrict__ A0, const float* __restrict__ A1,
    const float* __restrict__ A2, const float* __restrict__ A3,
    int d0, int d1, int d2, int d3,
    int c1, int c2, int c3)               // cumulative job counts after layers 0,1,2
{
    int b = blockIdx.x;
    int l, rel;
    if (b < c1)      { l = 0; rel = b; }
    else if (b < c2) { l = 1; rel = b - c1; }
    else if (b < c3) { l = 2; rel = b - c2; }
    else             { l = 3; rel = b - c3; }

    const float* lat = (l == 0) ? A0 : (l == 1) ? A1 : (l == 2) ? A2 : A3;
    int d = (l == 0) ? d0 : (l == 1) ? d1 : (l == 2) ? d2 : d3;
    int S0 = d0 / CHUNK, S1 = d1 / CHUNK, S2 = d2 / CHUNK;
    int slotBase = (l == 0) ? 0 : (l == 1) ? S0 : (l == 2) ? S0 + S1 : S0 + S1 + S2;

    int chunk = rel / 36;
    int tile  = rel % 36;
    int bx = tile % 6, by = tile / 6;
    int kBase = chunk * CHUNK;

    const float* A = lat;
    const float* B = lat + (size_t)N * d;
    float* out = &g_partial[(size_t)(slotBase + chunk) * NN];

    __shared__ float As[KT][TS + 4];
    __shared__ float Bs[KT][TS + 4];

    int tid = threadIdx.x;
    int tx = tid & 15, ty = tid >> 4;
    int row0 = by * TS, col0 = bx * TS;
    int lr = tid >> 2, lk = (tid & 3) * 4;

    float acc[4][4], hi[4][4];
    #pragma unroll
    for (int i = 0; i < 4; i++)
        #pragma unroll
        for (int j = 0; j < 4; j++) { acc[i][j] = 0.f; hi[i][j] = 0.f; }

    const int nt = CHUNK / KT;   // 256
    for (int it = 0; it < nt; it++) {
        int k0 = kBase + it * KT;
        float4 a = *(const float4*)(A + (size_t)(row0 + lr) * d + k0 + lk);
        float4 b4 = *(const float4*)(B + (size_t)(col0 + lr) * d + k0 + lk);
        __syncthreads();
        As[lk + 0][lr] = a.x;  As[lk + 1][lr] = a.y;  As[lk + 2][lr] = a.z;  As[lk + 3][lr] = a.w;
        Bs[lk + 0][lr] = b4.x; Bs[lk + 1][lr] = b4.y; Bs[lk + 2][lr] = b4.z; Bs[lk + 3][lr] = b4.w;
        __syncthreads();
        #pragma unroll
        for (int kk = 0; kk < KT; kk++) {
            float4 av = *(const float4*)&As[kk][ty * 4];
            float4 bv = *(const float4*)&Bs[kk][tx * 4];
            float aa[4] = {av.x, av.y, av.z, av.w};
            float bb[4] = {bv.x, bv.y, bv.z, bv.w};
            #pragma unroll
            for (int i = 0; i < 4; i++)
                #pragma unroll
                for (int j = 0; j < 4; j++)
                    acc[i][j] += aa[i] * bb[j];
        }
        if ((it & 15) == 15) {   // fold every 256 K for two-level accuracy
            #pragma unroll
            for (int i = 0; i < 4; i++)
                #pragma unroll
                for (int j = 0; j < 4; j++) { hi[i][j] += acc[i][j]; acc[i][j] = 0.f; }
        }
    }
    #pragma unroll
    for (int i = 0; i < 4; i++)
        #pragma unroll
        for (int j = 0; j < 4; j++) hi[i][j] += acc[i][j];

    #pragma unroll
    for (int i = 0; i < 4; i++) {
        int r = row0 + ty * 4 + i;
        #pragma unroll
        for (int j = 0; j < 4; j++) {
            int c = col0 + tx * 4 + j;
            out[r * N + c] = hi[i][j];
        }
    }
}

// ---------------- combine partials -> per-layer costs + combined (deterministic) ----------------
__global__ void combine_kernel(int d0, int d1, int d2, int d3) {
    int idx = blockIdx.x * blockDim.x + threadIdx.x;
    if (idx >= NN) return;
    int r = idx / N, c = idx % N;
    int S[4] = {d0 / CHUNK, d1 / CHUNK, d2 / CHUNK, d3 / CHUNK};
    int dd[4] = {d0, d1, d2, d3};
    const float wts[4] = {1.f, 0.5f, 0.25f, 0.125f};
    float comb = 0.f;
    int base = 0;
    #pragma unroll
    for (int l = 0; l < 4; l++) {
        float dot = 0.f;
        for (int ch = 0; ch < S[l]; ch++)
            dot += g_partial[(size_t)(base + ch) * NN + idx];
        base += S[l];
        float sq = (g_norms[2 * l * N + r] - 2.0f * dot) + g_norms[(2 * l + 1) * N + c];
        float cost = fmaxf(sq, 0.0f) * (1.0f / (float)dd[l]);
        g_cost[(size_t)l * NN + idx] = cost;
        comb = (l == 0) ? cost : comb + wts[l] * cost;   // ref fp32 order
    }
    g_cost[(size_t)4 * NN + idx] = comb;
}

// ---------------- sortable-u64 encoding of double (order-preserving) ----------------
__device__ __forceinline__ unsigned long long denc(double x) {
    unsigned long long u = (unsigned long long)__double_as_longlong(x);
    return (u & 0x8000000000000000ull) ? ~u : (u | 0x8000000000000000ull);
}
__device__ __forceinline__ double ddec(unsigned long long e) {
    unsigned long long u = (e & 0x8000000000000000ull) ? (e & 0x7fffffffffffffffull) : ~e;
    return __longlong_as_double((long long)u);
}

// ---------------- LAP (JV + column-reduction init, Dijkstra, fp64) : 1 block/matrix ----------------
__global__ void __launch_bounds__(N) lap_kernel() {
    int m = blockIdx.x;
    const float* __restrict__ C = &g_cost[(size_t)m * NN];

    __shared__ double u[N], v[N];
    __shared__ int matchRow[N];        // col -> row
    __shared__ int colOfRow[N];        // row -> col (-1 free)
    __shared__ int way[N];
    __shared__ int argRow[N];
    __shared__ int freeRows[N];
    __shared__ int s_nfree;
    __shared__ unsigned long long partEnc[2][12];
    __shared__ int partIdx[2][12];

    int j = threadIdx.x;

    // --- column reduction: v[j] = min_i C[i][j], greedy assignment ---
    {
        float cmin = C[j];
        int rmin = 0;
        #pragma unroll 8
        for (int i = 1; i < N; i++) {
            float cc = C[(size_t)i * N + j];
            if (cc < cmin) { cmin = cc; rmin = i; }
        }
        v[j] = (double)cmin;
        u[j] = 0.0;
        matchRow[j] = -1;
        colOfRow[j] = -1;
        argRow[j] = rmin;
    }
    __syncthreads();
    if (j == 0) {
        for (int c = 0; c < N; c++) {
            int r = argRow[c];
            if (colOfRow[r] < 0) { colOfRow[r] = c; matchRow[c] = r; }
        }
        int nf = 0;
        for (int r = 0; r < N; r++)
            if (colOfRow[r] < 0) freeRows[nf++] = r;
        s_nfree = nf;
    }
    __syncthreads();
    int nfree = s_nfree;

    double vj = v[j];

    for (int f = 0; f < nfree; f++) {
        int i = freeRows[f];
        double D = (double)C[(size_t)i * N + j] - vj;   // u[i] == 0 for free rows
        unsigned long long Denc = denc(D);
        way[j] = -1;
        bool vis = false;
        int sink = -1;
        double mind = 0.0;
        int buf = 0;
        __syncthreads();

        for (int iter = 0; iter <= N; iter++) {
            // warp-level argmin on sortable keys (tie-break: lowest index)
            unsigned long long key = vis ? ~0ull : Denc;
            int idx = j;
            #pragma unroll
            for (int off = 16; off; off >>= 1) {
                unsigned long long ok = __shfl_down_sync(0xffffffffu, key, off);
                int oi = __shfl_down_sync(0xffffffffu, idx, off);
                if (ok < key || (ok == key && oi < idx)) { key = ok; idx = oi; }
            }
            if ((j & 31) == 0) { partEnc[buf][j >> 5] = key; partIdx[buf][j >> 5] = idx; }
            __syncthreads();

            // every thread: gather partials, prefetch all 12 candidate cost rows,
            // and redundantly compute the global argmin (no 2nd barrier needed).
            unsigned long long pv[12];
            int pi[12], ci[12];
            float cw[12];
            #pragma unroll
            for (int w = 0; w < 12; w++) { pv[w] = partEnc[buf][w]; pi[w] = partIdx[buf][w]; }
            #pragma unroll
            for (int w = 0; w < 12; w++) ci[w] = matchRow[pi[w]];
            #pragma unroll
            for (int w = 0; w < 12; w++)
                cw[w] = (ci[w] >= 0) ? C[(size_t)ci[w] * N + j] : 0.0f;

            int bw = 0;
            #pragma unroll
            for (int w = 1; w < 12; w++)
                if (pv[w] < pv[bw] || (pv[w] == pv[bw] && pi[w] < pi[bw])) bw = w;

            int j1 = pi[bw];
            int i0 = ci[bw];
            mind = ddec(pv[bw]);
            if (i0 < 0) { sink = j1; break; }
            if (j == j1) vis = true;
            if (!vis) {
                double cand = mind + (double)cw[bw] - u[i0] - vj;
                if (cand < D) { D = cand; Denc = denc(D); way[j] = j1; }
            }
            buf ^= 1;
        }

        // dual updates (sink never marked visited)
        if (vis) {
            double dd = mind - D;
            vj -= dd;
            v[j] = vj;
            u[matchRow[j]] += dd;   // distinct rows per visited col: no conflict
        }
        if (j == 0) u[i] += mind;
        __syncthreads();            // duals done BEFORE augment mutates matchRow

        if (j == 0 && sink >= 0) {
            int jj = sink;
            while (true) {
                int pj = way[jj];
                if (pj < 0) { matchRow[jj] = i; break; }
                matchRow[jj] = matchRow[pj];
                jj = pj;
            }
        }
        __syncthreads();
    }

    g_rowcol[m * N + matchRow[j]] = j;   // row -> col
}

// ---------------- finalize: hamming total + outputs ----------------
__global__ void finalize_kernel(const long long* __restrict__ ipA,
                                const long long* __restrict__ ipB,
                                float* __restrict__ out, int out_size)
{
    __shared__ int idealcol[N];
    __shared__ int cnt[4];
    __shared__ float s_total;
    int t = threadIdx.x;
    if (t < 4) cnt[t] = 0;
    __syncthreads();
    idealcol[(int)ipA[t]] = (int)ipB[t];
    __syncthreads();
    #pragma unroll
    for (int l = 0; l < 4; l++)
        if (g_rowcol[l * N + t] == idealcol[t]) atomicAdd(&cnt[l], 1);
    __syncthreads();
    if (t == 0) {
        const double w[4] = {1.0, 0.5, 0.25, 0.125};
        double tot = 0.0;
        for (int l = 0; l < 4; l++)
            tot += w[l] * ((double)(2 * N - 2 * cnt[l]) / (double)N);
        s_total = (float)tot;
    }
    __syncthreads();
    float total = s_total;
    int colind = g_rowcol[4 * N + t];

    if (out_size >= 2 * N + 1) {
        if (t == 0) out[0] = total;
        out[1 + t] = (float)t;
        out[1 + N + t] = (float)colind;
        for (int idx = 2 * N + 1 + t; idx < out_size; idx += N) out[idx] = 0.0f;
    } else if (out_size == 2 * N) {
        out[t] = (float)t;
        out[N + t] = (float)colind;
    } else if (out_size >= 1) {
        if (t == 0) out[0] = total;
        for (int idx = 1 + t; idx < out_size; idx += N) out[idx] = 0.0f;
    }
}

// ---------------- launch ----------------
extern "C" void kernel_launch(void* const* d_in, const int* in_sizes, int n_in,
                              void* d_out, int out_size)
{
    const float* lat[4];
    int dims[4];
    for (int l = 0; l < 4; l++) {
        lat[l] = (const float*)d_in[l];
        dims[l] = in_sizes[l] / (2 * N);
    }
    const long long* ipA = (const long long*)d_in[4];
    const long long* ipB = (const long long*)d_in[5];

    int S0 = dims[0] / CHUNK, S1 = dims[1] / CHUNK, S2 = dims[2] / CHUNK, S3 = dims[3] / CHUNK;
    int c1 = 36 * S0, c2 = c1 + 36 * S1, c3 = c2 + 36 * S2, c4 = c3 + 36 * S3;

    norms_all_kernel<<<dim3(2 * N, 4), 128>>>(lat[0], lat[1], lat[2], lat[3],
                                              dims[0], dims[1], dims[2], dims[3]);
    gemm_partial_kernel<<<c4, 256>>>(lat[0], lat[1], lat[2], lat[3],
                                     dims[0], dims[1], dims[2], dims[3],
                                     c1, c2, c3);
    combine_kernel<<<(NN + 255) / 256, 256>>>(dims[0], dims[1], dims[2], dims[3]);
    lap_kernel<<<5, N>>>();
    finalize_kernel<<<1, N>>>(ipA, ipB, (float*)d_out, out_size);
}

// round 13
// speedup vs baseline: 1.6600x; 1.6593x over previous
#include <cuda_runtime.h>
#include <stdint.h>

#define N 384
#define NN (N * N)
#define SCALE_I 16777216.0f   // 2^24: exact integer embedding of fp32 costs

__device__ float g_norms[8 * N];
__device__ float g_seg[192 * NN];    // per-256K-segment partials (64+64+32+32)
__device__ int   g_costI[5 * NN];    // int32 fixed-point costs
__device__ int   g_rowcol[5 * N];

// ---- norms: identical arithmetic to the validated R3 pipeline ----
__global__ void norms_all_kernel(const float* __restrict__ A0, const float* __restrict__ A1,
                                 const float* __restrict__ A2, const float* __restrict__ A3,
                                 int d0, int d1, int d2, int d3)
{
    int layer = blockIdx.y;
    const float* src = (layer == 0) ? A0 : (layer == 1) ? A1 : (layer == 2) ? A2 : A3;
    int d = (layer == 0) ? d0 : (layer == 1) ? d1 : (layer == 2) ? d2 : d3;
    int side = blockIdx.x / N, row = blockIdx.x - side * N;
    const float* p = src + ((size_t)side * N + row) * d;
    int t = threadIdx.x;
    float hi = 0.f, lo = 0.f; int c = 0;
    for (int k = t; k < d; k += 128, c++) {
        float x = p[k]; lo += x * x;
        if ((c & 63) == 63) { hi += lo; lo = 0.f; }
    }
    hi += lo;
    __shared__ float s[4];
    #pragma unroll
    for (int off = 16; off; off >>= 1) hi += __shfl_down_sync(0xffffffffu, hi, off);
    if ((t & 31) == 0) s[t >> 5] = hi;
    __syncthreads();
    if (t == 0) g_norms[(2 * layer + side) * N + row] = (s[0] + s[1]) + (s[2] + s[3]);
}

// ---- gemm: one 128x128 tile x 256-K segment per CTA; straight ascending
// 256-term FFMA chain = R3's per-segment accumulation, bit-for-bit. ----
__global__ void __launch_bounds__(256) gemm_seg_kernel(
    const float* __restrict__ A0, const float* __restrict__ A1,
    const float* __restrict__ A2, const float* __restrict__ A3,
    int d0, int d1, int d2, int d3, int p0, int p1, int p2)   // seg prefix sums
{
    int seg = blockIdx.x / 9, tile = blockIdx.x % 9;
    int layer, base;
    if (seg < p0)      { layer = 0; base = 0; }
    else if (seg < p1) { layer = 1; base = p0; }
    else if (seg < p2) { layer = 2; base = p1; }
    else               { layer = 3; base = p2; }
    const float* lat = (layer == 0) ? A0 : (layer == 1) ? A1 : (layer == 2) ? A2 : A3;
    int d = (layer == 0) ? d0 : (layer == 1) ? d1 : (layer == 2) ? d2 : d3;
    int kBase = (seg - base) * 256;
    const float* A = lat;
    const float* B = lat + (size_t)N * d;
    float* out = &g_seg[(size_t)seg * NN];

    __shared__ float As[2][8][128], Bs[2][8][128];
    int t = threadIdx.x;
    int row0 = (tile / 3) * 128, col0 = (tile % 3) * 128;
    int lrow = t >> 1, lk4 = (t & 1) * 4;
    int ty = t >> 4, tx = t & 15;

    float acc[8][8];
    #pragma unroll
    for (int i = 0; i < 8; i++)
        #pragma unroll
        for (int j = 0; j < 8; j++) acc[i][j] = 0.f;

    const float* aPtr = A + (size_t)(row0 + lrow) * d + kBase + lk4;
    const float* bPtr = B + (size_t)(col0 + lrow) * d + kBase + lk4;
    float4 pa = *(const float4*)aPtr, pb = *(const float4*)bPtr;
    As[0][lk4+0][lrow]=pa.x; As[0][lk4+1][lrow]=pa.y; As[0][lk4+2][lrow]=pa.z; As[0][lk4+3][lrow]=pa.w;
    Bs[0][lk4+0][lrow]=pb.x; Bs[0][lk4+1][lrow]=pb.y; Bs[0][lk4+2][lrow]=pb.z; Bs[0][lk4+3][lrow]=pb.w;
    __syncthreads();

    const int nPan = 32;   // 32 x 8 = 256 K
    for (int p = 0; p < nPan; p++) {
        int buf = p & 1;
        if (p + 1 < nPan) {
            pa = *(const float4*)(aPtr + (p + 1) * 8);
            pb = *(const float4*)(bPtr + (p + 1) * 8);
        }
        #pragma unroll
        for (int kk = 0; kk < 8; kk++) {
            float4 a0 = *(const float4*)&As[buf][kk][ty*8];
            float4 a1 = *(const float4*)&As[buf][kk][ty*8+4];
            float4 b0 = *(const float4*)&Bs[buf][kk][tx*8];
            float4 b1 = *(const float4*)&Bs[buf][kk][tx*8+4];
            float ar[8] = {a0.x,a0.y,a0.z,a0.w,a1.x,a1.y,a1.z,a1.w};
            float br[8] = {b0.x,b0.y,b0.z,b0.w,b1.x,b1.y,b1.z,b1.w};
            #pragma unroll
            for (int i = 0; i < 8; i++)
                #pragma unroll
                for (int j = 0; j < 8; j++) acc[i][j] += ar[i] * br[j];
        }
        if (p + 1 < nPan) {
            int nb = buf ^ 1;
            As[nb][lk4+0][lrow]=pa.x; As[nb][lk4+1][lrow]=pa.y; As[nb][lk4+2][lrow]=pa.z; As[nb][lk4+3][lrow]=pa.w;
            Bs[nb][lk4+0][lrow]=pb.x; Bs[nb][lk4+1][lrow]=pb.y; Bs[nb][lk4+2][lrow]=pb.z; Bs[nb][lk4+3][lrow]=pb.w;
        }
        __syncthreads();
    }
    #pragma unroll
    for (int i = 0; i < 8; i++) {
        int r = row0 + ty * 8 + i;
        float4 o0 = {acc[i][0],acc[i][1],acc[i][2],acc[i][3]};
        float4 o1 = {acc[i][4],acc[i][5],acc[i][6],acc[i][7]};
        *(float4*)&out[(size_t)r * N + col0 + tx*8]     = o0;
        *(float4*)&out[(size_t)r * N + col0 + tx*8 + 4] = o1;
    }
}

// ---- combine: flat ascending segment sum = R3's ((s0+s1)+s2)+... bit-for-bit ----
__global__ void combine_kernel(int d0, int d1, int d2, int d3) {
    int idx = blockIdx.x * blockDim.x + threadIdx.x;
    if (idx >= NN) return;
    int r = idx / N, c = idx % N;
    int S[4] = {d0/256, d1/256, d2/256, d3/256};
    int dd[4] = {d0, d1, d2, d3};
    const float wts[4] = {1.f, 0.5f, 0.25f, 0.125f};
    float comb = 0.f; int base = 0;
    #pragma unroll
    for (int l = 0; l < 4; l++) {
        float dot = 0.f;
        for (int sg = 0; sg < S[l]; sg++) dot += g_seg[(size_t)(base+sg)*NN + idx];
        base += S[l];
        float sq = (g_norms[2*l*N + r] - 2.0f*dot) + g_norms[(2*l+1)*N + c];
        float cost = fmaxf(sq, 0.0f) * (1.0f / (float)dd[l]);
        g_costI[(size_t)l*NN + idx] = __float2int_rn(cost * SCALE_I);
        comb = (l == 0) ? cost : comb + wts[l] * cost;
    }
    g_costI[(size_t)4*NN + idx] = __float2int_rn(comb * SCALE_I);
}

__device__ __forceinline__ unsigned long long umin64(unsigned long long a, unsigned long long b){return a<b?a:b;}

// ---- LAP: exact int64 JV, ROW-SEQUENTIAL FROM u=v=0 (reference's exact
// augmenting order; R3-validated). One warp per matrix, zero barriers. ----
__global__ void __launch_bounds__(32) lap_kernel() {
    int m = blockIdx.x;
    const int* __restrict__ C = &g_costI[(size_t)m * NN];
    __shared__ long long u[N];
    __shared__ int matchRow[N], way[N];
    int lane = threadIdx.x;

    long long vr[12];
    #pragma unroll
    for (int s = 0; s < 12; s++) {
        int j = lane + 32 * s;
        vr[s] = 0; u[j] = 0; matchRow[j] = -1;
    }
    __syncwarp();

    for (int i = 0; i < N; i++) {
        const int* Ci = C + (size_t)i * N;
        long long D[12]; unsigned vis = 0;
        unsigned long long lb = ~0ull;
        #pragma unroll
        for (int s = 0; s < 12; s++) {
            int j = lane + 32 * s;
            D[s] = (long long)Ci[j] - vr[s];
            way[j] = -1;
            lb = umin64(lb, ((unsigned long long)D[s] << 9) | (unsigned)j);
        }
        unsigned long long best = lb;
        #pragma unroll
        for (int o = 16; o; o >>= 1)
            best = umin64(best, __shfl_xor_sync(0xffffffffu, best, o));

        int sink = -1, j1 = 0, i0;
        long long mind = 0;
        for (int iter = 0; iter <= N; iter++) {
            j1 = (int)(best & 511);
            mind = (long long)(best >> 9);
            i0 = matchRow[j1];
            if (i0 < 0) { sink = j1; break; }
            if ((j1 & 31) == lane) vis |= 1u << (j1 >> 5);
            long long off = mind - u[i0];
            const int* Cr = C + (size_t)i0 * N;
            int cc[12];
            #pragma unroll
            for (int s = 0; s < 12; s++) cc[s] = Cr[lane + 32 * s];
            lb = ~0ull;
            #pragma unroll
            for (int s = 0; s < 12; s++) {
                if (!((vis >> s) & 1)) {
                    int j = lane + 32 * s;
                    long long cand = off + (long long)cc[s] - vr[s];
                    if (cand < D[s]) { D[s] = cand; way[j] = j1; }
                    lb = umin64(lb, ((unsigned long long)D[s] << 9) | (unsigned)j);
                }
            }
            best = lb;
            #pragma unroll
            for (int o = 16; o; o >>= 1)
                best = umin64(best, __shfl_xor_sync(0xffffffffu, best, o));
        }

        #pragma unroll
        for (int s = 0; s < 12; s++) {
            if ((vis >> s) & 1) {
                int j = lane + 32 * s;
                long long dd = mind - D[s];
                vr[s] -= dd;
                u[matchRow[j]] += dd;      // distinct rows per visited col
            }
        }
        if (lane == 0) u[i] += mind;
        __syncwarp();
        if (lane == 0 && sink >= 0) {
            int jj = sink, guard = 0;
            while (guard++ <= N) {
                int pj = way[jj];
                int prev = (pj < 0) ? i : matchRow[pj];
                matchRow[jj] = prev;
                if (pj < 0) break;
                jj = pj;
            }
        }
        __syncwarp();
    }
    #pragma unroll
    for (int s = 0; s < 12; s++) {
        int j = lane + 32 * s;
        int r = matchRow[j];
        if (r >= 0) g_rowcol[m * N + r] = j;
    }
}

__global__ void finalize_kernel(const long long* __restrict__ ipA,
                                const long long* __restrict__ ipB,
                                float* __restrict__ out, int out_size)
{
    __shared__ int idealcol[N];
    __shared__ int cnt[4];
    __shared__ float s_total;
    int t = threadIdx.x;
    if (t < 4) cnt[t] = 0;
    __syncthreads();
    idealcol[(int)ipA[t]] = (int)ipB[t];
    __syncthreads();
    #pragma unroll
    for (int l = 0; l < 4; l++)
        if (g_rowcol[l * N + t] == idealcol[t]) atomicAdd(&cnt[l], 1);
    __syncthreads();
    if (t == 0) {
        const double w[4] = {1.0, 0.5, 0.25, 0.125};
        double tot = 0.0;
        for (int l = 0; l < 4; l++)
            tot += w[l] * ((double)(2 * N - 2 * cnt[l]) / (double)N);
        s_total = (float)tot;
    }
    __syncthreads();
    float total = s_total;
    int colind = g_rowcol[4 * N + t];
    if (out_size >= 2 * N + 1) {
        if (t == 0) out[0] = total;
        out[1 + t] = (float)t;
        out[1 + N + t] = (float)colind;
        for (int idx = 2 * N + 1 + t; idx < out_size; idx += N) out[idx] = 0.0f;
    } else if (out_size == 2 * N) {
        out[t] = (float)t;
        out[N + t] = (float)colind;
    } else if (out_size >= 1) {
        if (t == 0) out[0] = total;
        for (int idx = 1 + t; idx < out_size; idx += N) out[idx] = 0.0f;
    }
}

extern "C" void kernel_launch(void* const* d_in, const int* in_sizes, int n_in,
                              void* d_out, int out_size)
{
    const float* lat[4]; int dims[4];
    for (int l = 0; l < 4; l++) {
        lat[l] = (const float*)d_in[l];
        dims[l] = in_sizes[l] / (2 * N);
    }
    const long long* ipA = (const long long*)d_in[4];
    const long long* ipB = (const long long*)d_in[5];
    int S0 = dims[0]/256, S1 = dims[1]/256, S2 = dims[2]/256, S3 = dims[3]/256;
    int p0 = S0, p1 = p0 + S1, p2 = p1 + S2, totSeg = p2 + S3;

    norms_all_kernel<<<dim3(2 * N, 4), 128>>>(lat[0], lat[1], lat[2], lat[3],
                                              dims[0], dims[1], dims[2], dims[3]);
    gemm_seg_kernel<<<totSeg * 9, 256>>>(lat[0], lat[1], lat[2], lat[3],
                                         dims[0], dims[1], dims[2], dims[3], p0, p1, p2);
    combine_kernel<<<(NN + 255) / 256, 256>>>(dims[0], dims[1], dims[2], dims[3]);
    lap_kernel<<<5, 32>>>();
    finalize_kernel<<<1, N>>>(ipA, ipB, (float*)d_out, out_size);
}

// round 14
// speedup vs baseline: 1.7393x; 1.0478x over previous
#include <cuda_runtime.h>
#include <stdint.h>

#define N 384
#define NN (N * N)
#define SCALE_I 16777216.0f   // 2^24: exact integer embedding of fp32 costs

__device__ float g_norms[8 * N];
__device__ float g_seg[192 * NN];    // per-256K-segment partials (64+64+32+32)
__device__ int   g_costI[5 * NN];    // int32 fixed-point costs
__device__ int   g_rowcol[5 * N];

// ---- norms: identical arithmetic to the validated R13 pipeline ----
__global__ void norms_all_kernel(const float* __restrict__ A0, const float* __restrict__ A1,
                                 const float* __restrict__ A2, const float* __restrict__ A3,
                                 int d0, int d1, int d2, int d3)
{
    int layer = blockIdx.y;
    const float* src = (layer == 0) ? A0 : (layer == 1) ? A1 : (layer == 2) ? A2 : A3;
    int d = (layer == 0) ? d0 : (layer == 1) ? d1 : (layer == 2) ? d2 : d3;
    int side = blockIdx.x / N, row = blockIdx.x - side * N;
    const float* p = src + ((size_t)side * N + row) * d;
    int t = threadIdx.x;
    float hi = 0.f, lo = 0.f; int c = 0;
    for (int k = t; k < d; k += 128, c++) {
        float x = p[k]; lo += x * x;
        if ((c & 63) == 63) { hi += lo; lo = 0.f; }
    }
    hi += lo;
    __shared__ float s[4];
    #pragma unroll
    for (int off = 16; off; off >>= 1) hi += __shfl_down_sync(0xffffffffu, hi, off);
    if ((t & 31) == 0) s[t >> 5] = hi;
    __syncthreads();
    if (t == 0) g_norms[(2 * layer + side) * N + row] = (s[0] + s[1]) + (s[2] + s[3]);
}

// ---- gemm: byte-identical to R13 (cost bits are frozen) ----
__global__ void __launch_bounds__(256) gemm_seg_kernel(
    const float* __restrict__ A0, const float* __restrict__ A1,
    const float* __restrict__ A2, const float* __restrict__ A3,
    int d0, int d1, int d2, int d3, int p0, int p1, int p2)
{
    int seg = blockIdx.x / 9, tile = blockIdx.x % 9;
    int layer, base;
    if (seg < p0)      { layer = 0; base = 0; }
    else if (seg < p1) { layer = 1; base = p0; }
    else if (seg < p2) { layer = 2; base = p1; }
    else               { layer = 3; base = p2; }
    const float* lat = (layer == 0) ? A0 : (layer == 1) ? A1 : (layer == 2) ? A2 : A3;
    int d = (layer == 0) ? d0 : (layer == 1) ? d1 : (layer == 2) ? d2 : d3;
    int kBase = (seg - base) * 256;
    const float* A = lat;
    const float* B = lat + (size_t)N * d;
    float* out = &g_seg[(size_t)seg * NN];

    __shared__ float As[2][8][128], Bs[2][8][128];
    int t = threadIdx.x;
    int row0 = (tile / 3) * 128, col0 = (tile % 3) * 128;
    int lrow = t >> 1, lk4 = (t & 1) * 4;
    int ty = t >> 4, tx = t & 15;

    float acc[8][8];
    #pragma unroll
    for (int i = 0; i < 8; i++)
        #pragma unroll
        for (int j = 0; j < 8; j++) acc[i][j] = 0.f;

    const float* aPtr = A + (size_t)(row0 + lrow) * d + kBase + lk4;
    const float* bPtr = B + (size_t)(col0 + lrow) * d + kBase + lk4;
    float4 pa = *(const float4*)aPtr, pb = *(const float4*)bPtr;
    As[0][lk4+0][lrow]=pa.x; As[0][lk4+1][lrow]=pa.y; As[0][lk4+2][lrow]=pa.z; As[0][lk4+3][lrow]=pa.w;
    Bs[0][lk4+0][lrow]=pb.x; Bs[0][lk4+1][lrow]=pb.y; Bs[0][lk4+2][lrow]=pb.z; Bs[0][lk4+3][lrow]=pb.w;
    __syncthreads();

    const int nPan = 32;
    for (int p = 0; p < nPan; p++) {
        int buf = p & 1;
        if (p + 1 < nPan) {
            pa = *(const float4*)(aPtr + (p + 1) * 8);
            pb = *(const float4*)(bPtr + (p + 1) * 8);
        }
        #pragma unroll
        for (int kk = 0; kk < 8; kk++) {
            float4 a0 = *(const float4*)&As[buf][kk][ty*8];
            float4 a1 = *(const float4*)&As[buf][kk][ty*8+4];
            float4 b0 = *(const float4*)&Bs[buf][kk][tx*8];
            float4 b1 = *(const float4*)&Bs[buf][kk][tx*8+4];
            float ar[8] = {a0.x,a0.y,a0.z,a0.w,a1.x,a1.y,a1.z,a1.w};
            float br[8] = {b0.x,b0.y,b0.z,b0.w,b1.x,b1.y,b1.z,b1.w};
            #pragma unroll
            for (int i = 0; i < 8; i++)
                #pragma unroll
                for (int j = 0; j < 8; j++) acc[i][j] += ar[i] * br[j];
        }
        if (p + 1 < nPan) {
            int nb = buf ^ 1;
            As[nb][lk4+0][lrow]=pa.x; As[nb][lk4+1][lrow]=pa.y; As[nb][lk4+2][lrow]=pa.z; As[nb][lk4+3][lrow]=pa.w;
            Bs[nb][lk4+0][lrow]=pb.x; Bs[nb][lk4+1][lrow]=pb.y; Bs[nb][lk4+2][lrow]=pb.z; Bs[nb][lk4+3][lrow]=pb.w;
        }
        __syncthreads();
    }
    #pragma unroll
    for (int i = 0; i < 8; i++) {
        int r = row0 + ty * 8 + i;
        float4 o0 = {acc[i][0],acc[i][1],acc[i][2],acc[i][3]};
        float4 o1 = {acc[i][4],acc[i][5],acc[i][6],acc[i][7]};
        *(float4*)&out[(size_t)r * N + col0 + tx*8]     = o0;
        *(float4*)&out[(size_t)r * N + col0 + tx*8 + 4] = o1;
    }
}

// ---- combine: byte-identical to R13 (cost bits frozen) ----
__global__ void combine_kernel(int d0, int d1, int d2, int d3) {
    int idx = blockIdx.x * blockDim.x + threadIdx.x;
    if (idx >= NN) return;
    int r = idx / N, c = idx % N;
    int S[4] = {d0/256, d1/256, d2/256, d3/256};
    int dd[4] = {d0, d1, d2, d3};
    const float wts[4] = {1.f, 0.5f, 0.25f, 0.125f};
    float comb = 0.f; int base = 0;
    #pragma unroll
    for (int l = 0; l < 4; l++) {
        float dot = 0.f;
        for (int sg = 0; sg < S[l]; sg++) dot += g_seg[(size_t)(base+sg)*NN + idx];
        base += S[l];
        float sq = (g_norms[2*l*N + r] - 2.0f*dot) + g_norms[(2*l+1)*N + c];
        float cost = fmaxf(sq, 0.0f) * (1.0f / (float)dd[l]);
        g_costI[(size_t)l*NN + idx] = __float2int_rn(cost * SCALE_I);
        comb = (l == 0) ? cost : comb + wts[l] * cost;
    }
    g_costI[(size_t)4*NN + idx] = __float2int_rn(comb * SCALE_I);
}

__device__ __forceinline__ unsigned long long umin64(unsigned long long a, unsigned long long b){return a<b?a:b;}

// ---- LAP: exact int64 JV, row-sequential from u=v=0 (R13-validated order).
// New mechanics only: lane owns cols j = 128*s + 4*lane + e (q = s*4+e),
// rows loaded as 3x LDG.128 via __ldg (L1-cached). Same keys, same tie-break. ----
__global__ void __launch_bounds__(32) lap_kernel() {
    int m = blockIdx.x;
    const int* __restrict__ C = &g_costI[(size_t)m * NN];
    __shared__ long long u[N];
    __shared__ int matchRow[N], way[N];
    int lane = threadIdx.x;

    long long vr[12];                 // q = s*4 + e  ->  col j = 128*s + 4*lane + e
    #pragma unroll
    for (int q = 0; q < 12; q++) vr[q] = 0;
    #pragma unroll
    for (int s = 0; s < 12; s++) {
        int j = lane + 32 * s;
        u[j] = 0; matchRow[j] = -1;
    }
    __syncwarp();

    for (int i = 0; i < N; i++) {
        const int4* Ci = (const int4*)(C + (size_t)i * N);
        long long D[12]; unsigned vis = 0;
        unsigned long long lb = ~0ull;
        #pragma unroll
        for (int s = 0; s < 3; s++) {
            int4 cc = __ldg(Ci + s * 32 + lane);
            int bj = 128 * s + 4 * lane;
            int v0 = cc.x, v1 = cc.y, v2 = cc.z, v3 = cc.w;
            D[s*4+0] = (long long)v0 - vr[s*4+0];
            D[s*4+1] = (long long)v1 - vr[s*4+1];
            D[s*4+2] = (long long)v2 - vr[s*4+2];
            D[s*4+3] = (long long)v3 - vr[s*4+3];
            way[bj+0] = -1; way[bj+1] = -1; way[bj+2] = -1; way[bj+3] = -1;
            #pragma unroll
            for (int e = 0; e < 4; e++)
                lb = umin64(lb, ((unsigned long long)D[s*4+e] << 9) | (unsigned)(bj + e));
        }
        unsigned long long best = lb;
        #pragma unroll
        for (int o = 16; o; o >>= 1)
            best = umin64(best, __shfl_xor_sync(0xffffffffu, best, o));

        int sink = -1;
        long long mind = 0;
        for (int iter = 0; iter <= N; iter++) {
            int j1 = (int)(best & 511);
            mind = (long long)(best >> 9);
            int i0 = matchRow[j1];
            if (i0 < 0) { sink = j1; break; }
            if (((j1 >> 2) & 31) == lane) vis |= 1u << (((j1 >> 7) << 2) | (j1 & 3));
            long long off = mind - u[i0];
            const int4* Cr = (const int4*)(C + (size_t)i0 * N);
            int4 c0 = __ldg(Cr + lane);
            int4 c1 = __ldg(Cr + 32 + lane);
            int4 c2 = __ldg(Cr + 64 + lane);
            int cc[12] = {c0.x, c0.y, c0.z, c0.w,
                          c1.x, c1.y, c1.z, c1.w,
                          c2.x, c2.y, c2.z, c2.w};
            lb = ~0ull;
            #pragma unroll
            for (int q = 0; q < 12; q++) {
                if (!((vis >> q) & 1)) {
                    int j = 128 * (q >> 2) + 4 * lane + (q & 3);
                    long long cand = off + (long long)cc[q] - vr[q];
                    if (cand < D[q]) { D[q] = cand; way[j] = j1; }
                    lb = umin64(lb, ((unsigned long long)D[q] << 9) | (unsigned)j);
                }
            }
            best = lb;
            #pragma unroll
            for (int o = 16; o; o >>= 1)
                best = umin64(best, __shfl_xor_sync(0xffffffffu, best, o));
        }

        #pragma unroll
        for (int q = 0; q < 12; q++) {
            if ((vis >> q) & 1) {
                int j = 128 * (q >> 2) + 4 * lane + (q & 3);
                long long dd = mind - D[q];
                vr[q] -= dd;
                u[matchRow[j]] += dd;      // distinct rows per visited col
            }
        }
        if (lane == 0) u[i] += mind;
        __syncwarp();
        if (lane == 0 && sink >= 0) {
            int jj = sink, guard = 0;
            while (guard++ <= N) {
                int pj = way[jj];
                int prev = (pj < 0) ? i : matchRow[pj];
                matchRow[jj] = prev;
                if (pj < 0) break;
                jj = pj;
            }
        }
        __syncwarp();
    }
    #pragma unroll
    for (int s = 0; s < 12; s++) {
        int j = lane + 32 * s;
        int r = matchRow[j];
        if (r >= 0) g_rowcol[m * N + r] = j;
    }
}

__global__ void finalize_kernel(const long long* __restrict__ ipA,
                                const long long* __restrict__ ipB,
                                float* __restrict__ out, int out_size)
{
    __shared__ int idealcol[N];
    __shared__ int cnt[4];
    __shared__ float s_total;
    int t = threadIdx.x;
    if (t < 4) cnt[t] = 0;
    __syncthreads();
    idealcol[(int)ipA[t]] = (int)ipB[t];
    __syncthreads();
    #pragma unroll
    for (int l = 0; l < 4; l++)
        if (g_rowcol[l * N + t] == idealcol[t]) atomicAdd(&cnt[l], 1);
    __syncthreads();
    if (t == 0) {
        const double w[4] = {1.0, 0.5, 0.25, 0.125};
        double tot = 0.0;
        for (int l = 0; l < 4; l++)
            tot += w[l] * ((double)(2 * N - 2 * cnt[l]) / (double)N);
        s_total = (float)tot;
    }
    __syncthreads();
    float total = s_total;
    int colind = g_rowcol[4 * N + t];
    if (out_size >= 2 * N + 1) {
        if (t == 0) out[0] = total;
        out[1 + t] = (float)t;
        out[1 + N + t] = (float)colind;
        for (int idx = 2 * N + 1 + t; idx < out_size; idx += N) out[idx] = 0.0f;
    } else if (out_size == 2 * N) {
        out[t] = (float)t;
        out[N + t] = (float)colind;
    } else if (out_size >= 1) {
        if (t == 0) out[0] = total;
        for (int idx = 1 + t; idx < out_size; idx += N) out[idx] = 0.0f;
    }
}

extern "C" void kernel_launch(void* const* d_in, const int* in_sizes, int n_in,
                              void* d_out, int out_size)
{
    const float* lat[4]; int dims[4];
    for (int l = 0; l < 4; l++) {
        lat[l] = (const float*)d_in[l];
        dims[l] = in_sizes[l] / (2 * N);
    }
    const long long* ipA = (const long long*)d_in[4];
    const long long* ipB = (const long long*)d_in[5];
    int S0 = dims[0]/256, S1 = dims[1]/256, S2 = dims[2]/256, S3 = dims[3]/256;
    int p0 = S0, p1 = p0 + S1, p2 = p1 + S2, totSeg = p2 + S3;

    norms_all_kernel<<<dim3(2 * N, 4), 128>>>(lat[0], lat[1], lat[2], lat[3],
                                              dims[0], dims[1], dims[2], dims[3]);
    gemm_seg_kernel<<<totSeg * 9, 256>>>(lat[0], lat[1], lat[2], lat[3],
                                         dims[0], dims[1], dims[2], dims[3], p0, p1, p2);
    combine_kernel<<<(NN + 255) / 256, 256>>>(dims[0], dims[1], dims[2], dims[3]);
    lap_kernel<<<5, 32>>>();
    finalize_kernel<<<1, N>>>(ipA, ipB, (float*)d_out, out_size);
}

// round 16
// speedup vs baseline: 2.0583x; 1.1834x over previous
#include <cuda_runtime.h>
#include <stdint.h>

#define N 384
#define NN (N * N)
#define SCALE_I 16777216.0f   // 2^24: exact integer embedding of fp32 costs

__device__ float g_norms[8 * N];
__device__ float g_seg[192 * NN];    // per-256K-segment partials (64+64+32+32)
__device__ int   g_costI[5 * NN];    // int32 fixed-point costs
__device__ int   g_rowcol[5 * N];

// ---- norms: identical arithmetic to the validated R13 pipeline ----
__global__ void norms_all_kernel(const float* __restrict__ A0, const float* __restrict__ A1,
                                 const float* __restrict__ A2, const float* __restrict__ A3,
                                 int d0, int d1, int d2, int d3)
{
    int layer = blockIdx.y;
    const float* src = (layer == 0) ? A0 : (layer == 1) ? A1 : (layer == 2) ? A2 : A3;
    int d = (layer == 0) ? d0 : (layer == 1) ? d1 : (layer == 2) ? d2 : d3;
    int side = blockIdx.x / N, row = blockIdx.x - side * N;
    const float* p = src + ((size_t)side * N + row) * d;
    int t = threadIdx.x;
    float hi = 0.f, lo = 0.f; int c = 0;
    for (int k = t; k < d; k += 128, c++) {
        float x = p[k]; lo += x * x;
        if ((c & 63) == 63) { hi += lo; lo = 0.f; }
    }
    hi += lo;
    __shared__ float s[4];
    #pragma unroll
    for (int off = 16; off; off >>= 1) hi += __shfl_down_sync(0xffffffffu, hi, off);
    if ((t & 31) == 0) s[t >> 5] = hi;
    __syncthreads();
    if (t == 0) g_norms[(2 * layer + side) * N + row] = (s[0] + s[1]) + (s[2] + s[3]);
}

// ---- gemm: byte-identical to R13/R14 (cost bits are frozen) ----
__global__ void __launch_bounds__(256) gemm_seg_kernel(
    const float* __restrict__ A0, const float* __restrict__ A1,
    const float* __restrict__ A2, const float* __restrict__ A3,
    int d0, int d1, int d2, int d3, int p0, int p1, int p2)
{
    int seg = blockIdx.x / 9, tile = blockIdx.x % 9;
    int layer, base;
    if (seg < p0)      { layer = 0; base = 0; }
    else if (seg < p1) { layer = 1; base = p0; }
    else if (seg < p2) { layer = 2; base = p1; }
    else               { layer = 3; base = p2; }
    const float* lat = (layer == 0) ? A0 : (layer == 1) ? A1 : (layer == 2) ? A2 : A3;
    int d = (layer == 0) ? d0 : (layer == 1) ? d1 : (layer == 2) ? d2 : d3;
    int kBase = (seg - base) * 256;
    const float* A = lat;
    const float* B = lat + (size_t)N * d;
    float* out = &g_seg[(size_t)seg * NN];

    __shared__ float As[2][8][128], Bs[2][8][128];
    int t = threadIdx.x;
    int row0 = (tile / 3) * 128, col0 = (tile % 3) * 128;
    int lrow = t >> 1, lk4 = (t & 1) * 4;
    int ty = t >> 4, tx = t & 15;

    float acc[8][8];
    #pragma unroll
    for (int i = 0; i < 8; i++)
        #pragma unroll
        for (int j = 0; j < 8; j++) acc[i][j] = 0.f;

    const float* aPtr = A + (size_t)(row0 + lrow) * d + kBase + lk4;
    const float* bPtr = B + (size_t)(col0 + lrow) * d + kBase + lk4;
    float4 pa = *(const float4*)aPtr, pb = *(const float4*)bPtr;
    As[0][lk4+0][lrow]=pa.x; As[0][lk4+1][lrow]=pa.y; As[0][lk4+2][lrow]=pa.z; As[0][lk4+3][lrow]=pa.w;
    Bs[0][lk4+0][lrow]=pb.x; Bs[0][lk4+1][lrow]=pb.y; Bs[0][lk4+2][lrow]=pb.z; Bs[0][lk4+3][lrow]=pb.w;
    __syncthreads();

    const int nPan = 32;
    for (int p = 0; p < nPan; p++) {
        int buf = p & 1;
        if (p + 1 < nPan) {
            pa = *(const float4*)(aPtr + (p + 1) * 8);
            pb = *(const float4*)(bPtr + (p + 1) * 8);
        }
        #pragma unroll
        for (int kk = 0; kk < 8; kk++) {
            float4 a0 = *(const float4*)&As[buf][kk][ty*8];
            float4 a1 = *(const float4*)&As[buf][kk][ty*8+4];
            float4 b0 = *(const float4*)&Bs[buf][kk][tx*8];
            float4 b1 = *(const float4*)&Bs[buf][kk][tx*8+4];
            float ar[8] = {a0.x,a0.y,a0.z,a0.w,a1.x,a1.y,a1.z,a1.w};
            float br[8] = {b0.x,b0.y,b0.z,b0.w,b1.x,b1.y,b1.z,b1.w};
            #pragma unroll
            for (int i = 0; i < 8; i++)
                #pragma unroll
                for (int j = 0; j < 8; j++) acc[i][j] += ar[i] * br[j];
        }
        if (p + 1 < nPan) {
            int nb = buf ^ 1;
            As[nb][lk4+0][lrow]=pa.x; As[nb][lk4+1][lrow]=pa.y; As[nb][lk4+2][lrow]=pa.z; As[nb][lk4+3][lrow]=pa.w;
            Bs[nb][lk4+0][lrow]=pb.x; Bs[nb][lk4+1][lrow]=pb.y; Bs[nb][lk4+2][lrow]=pb.z; Bs[nb][lk4+3][lrow]=pb.w;
        }
        __syncthreads();
    }
    #pragma unroll
    for (int i = 0; i < 8; i++) {
        int r = row0 + ty * 8 + i;
        float4 o0 = {acc[i][0],acc[i][1],acc[i][2],acc[i][3]};
        float4 o1 = {acc[i][4],acc[i][5],acc[i][6],acc[i][7]};
        *(float4*)&out[(size_t)r * N + col0 + tx*8]     = o0;
        *(float4*)&out[(size_t)r * N + col0 + tx*8 + 4] = o1;
    }
}

// ---- combine: byte-identical to R13/R14 (cost bits frozen) ----
__global__ void combine_kernel(int d0, int d1, int d2, int d3) {
    int idx = blockIdx.x * blockDim.x + threadIdx.x;
    if (idx >= NN) return;
    int r = idx / N, c = idx % N;
    int S[4] = {d0/256, d1/256, d2/256, d3/256};
    int dd[4] = {d0, d1, d2, d3};
    const float wts[4] = {1.f, 0.5f, 0.25f, 0.125f};
    float comb = 0.f; int base = 0;
    #pragma unroll
    for (int l = 0; l < 4; l++) {
        float dot = 0.f;
        for (int sg = 0; sg < S[l]; sg++) dot += g_seg[(size_t)(base+sg)*NN + idx];
        base += S[l];
        float sq = (g_norms[2*l*N + r] - 2.0f*dot) + g_norms[(2*l+1)*N + c];
        float cost = fmaxf(sq, 0.0f) * (1.0f / (float)dd[l]);
        g_costI[(size_t)l*NN + idx] = __float2int_rn(cost * SCALE_I);
        comb = (l == 0) ? cost : comb + wts[l] * cost;
    }
    g_costI[(size_t)4*NN + idx] = __float2int_rn(comb * SCALE_I);
}

__device__ __forceinline__ unsigned long long umin64(unsigned long long a, unsigned long long b){return a<b?a:b;}

// Lexicographic warp-min of 64-bit keys via two 32-bit REDUX ops.
__device__ __forceinline__ unsigned long long warp_min_key(unsigned long long lb) {
    unsigned hi = (unsigned)(lb >> 32);
    unsigned mh = __reduce_min_sync(0xffffffffu, hi);
    unsigned lo = (hi == mh) ? (unsigned)lb : 0xffffffffu;
    unsigned ml = __reduce_min_sync(0xffffffffu, lo);
    return ((unsigned long long)mh << 32) | ml;
}

// ---- LAP: exact int64 JV, row-sequential from u=v=0 (validated order).
// key = (D<<18) | (j<<9) | (matchRow[j]+1): ties in D break by lowest j
// (identical selection); i0 rides in the key (no LDS on critical path).
// Visited cols: key=INF; relax needs no guard (cand >= mind >= D[visited]).
__global__ void __launch_bounds__(32) lap_kernel() {
    int m = blockIdx.x;
    const int* __restrict__ C = &g_costI[(size_t)m * NN];
    __shared__ long long u[N];
    __shared__ int matchRow[N], way[N];
    int lane = threadIdx.x;
    const unsigned long long INFK = ~0ull;

    long long vr[12];                 // q = s*4 + e -> col j = 128*s + 4*lane + e
    #pragma unroll
    for (int q = 0; q < 12; q++) vr[q] = 0;
    #pragma unroll
    for (int s = 0; s < 12; s++) {
        int j = lane + 32 * s;
        u[j] = 0; matchRow[j] = -1;
    }
    __syncwarp();

    for (int i = 0; i < N; i++) {
        const int4* Ci = (const int4*)(C + (size_t)i * N);
        long long D[12];
        unsigned long long key[12];
        unsigned tag[12];
        unsigned vis = 0;

        #pragma unroll
        for (int q = 0; q < 12; q++) {
            int j = 128 * (q >> 2) + 4 * lane + (q & 3);
            tag[q] = ((unsigned)j << 9) | (unsigned)(matchRow[j] + 1);
        }
        unsigned long long lb = INFK;
        #pragma unroll
        for (int s = 0; s < 3; s++) {
            int4 cc = __ldg(Ci + s * 32 + lane);
            int bj = 128 * s + 4 * lane;
            int v4[4] = {cc.x, cc.y, cc.z, cc.w};
            way[bj+0] = -1; way[bj+1] = -1; way[bj+2] = -1; way[bj+3] = -1;
            #pragma unroll
            for (int e = 0; e < 4; e++) {
                int q = s * 4 + e;
                D[q] = (long long)v4[e] - vr[q];
                key[q] = ((unsigned long long)D[q] << 18) | tag[q];
                lb = umin64(lb, key[q]);
            }
        }
        unsigned long long best = warp_min_key(lb);

        int sink = -1;
        long long mind = 0;
        for (int iter = 0; iter <= N; iter++) {
            int j1 = (int)((best >> 9) & 511);
            int i0 = (int)(best & 511) - 1;
            mind = (long long)(best >> 18);
            if (i0 < 0) { sink = j1; break; }
            int ql = ((j1 >> 7) << 2) | (j1 & 3);
            if (((j1 >> 2) & 31) == lane) { vis |= 1u << ql; key[ql] = INFK; }
            long long off = mind - u[i0];
            const int4* Cr = (const int4*)(C + (size_t)i0 * N);
            int4 c0 = __ldg(Cr + lane);
            int4 c1 = __ldg(Cr + 32 + lane);
            int4 c2 = __ldg(Cr + 64 + lane);
            int cc[12] = {c0.x, c0.y, c0.z, c0.w,
                          c1.x, c1.y, c1.z, c1.w,
                          c2.x, c2.y, c2.z, c2.w};
            lb = INFK;
            #pragma unroll
            for (int q = 0; q < 12; q++) {
                long long cand = off + (long long)cc[q] - vr[q];
                if (cand < D[q]) {
                    D[q] = cand;
                    way[128 * (q >> 2) + 4 * lane + (q & 3)] = j1;
                    key[q] = ((unsigned long long)cand << 18) | tag[q];
                }
                lb = umin64(lb, key[q]);
            }
            best = warp_min_key(lb);
        }

        #pragma unroll
        for (int q = 0; q < 12; q++) {
            if ((vis >> q) & 1) {
                int j = 128 * (q >> 2) + 4 * lane + (q & 3);
                long long dd = mind - D[q];
                vr[q] -= dd;
                u[matchRow[j]] += dd;      // distinct rows per visited col
            }
        }
        if (lane == 0) u[i] += mind;
        __syncwarp();
        if (lane == 0 && sink >= 0) {
            int jj = sink, guard = 0;
            while (guard++ <= N) {
                int pj = way[jj];
                int prev = (pj < 0) ? i : matchRow[pj];
                matchRow[jj] = prev;
                if (pj < 0) break;
                jj = pj;
            }
        }
        __syncwarp();
    }
    #pragma unroll
    for (int s = 0; s < 12; s++) {
        int j = lane + 32 * s;
        int r = matchRow[j];
        if (r >= 0) g_rowcol[m * N + r] = j;
    }
}

__global__ void finalize_kernel(const long long* __restrict__ ipA,
                                const long long* __restrict__ ipB,
                                float* __restrict__ out, int out_size)
{
    __shared__ int idealcol[N];
    __shared__ int cnt[4];
    __shared__ float s_total;
    int t = threadIdx.x;
    if (t < 4) cnt[t] = 0;
    __syncthreads();
    idealcol[(int)ipA[t]] = (int)ipB[t];
    __syncthreads();
    #pragma unroll
    for (int l = 0; l < 4; l++)
        if (g_rowcol[l * N + t] == idealcol[t]) atomicAdd(&cnt[l], 1);
    __syncthreads();
    if (t == 0) {
        const double w[4] = {1.0, 0.5, 0.25, 0.125};
        double tot = 0.0;
        for (int l = 0; l < 4; l++)
            tot += w[l] * ((double)(2 * N - 2 * cnt[l]) / (double)N);
        s_total = (float)tot;
    }
    __syncthreads();
    float total = s_total;
    int colind = g_rowcol[4 * N + t];
    if (out_size >= 2 * N + 1) {
        if (t == 0) out[0] = total;
        out[1 + t] = (float)t;
        out[1 + N + t] = (float)colind;
        for (int idx = 2 * N + 1 + t; idx < out_size; idx += N) out[idx] = 0.0f;
    } else if (out_size == 2 * N) {
        out[t] = (float)t;
        out[N + t] = (float)colind;
    } else if (out_size >= 1) {
        if (t == 0) out[0] = total;
        for (int idx = 1 + t; idx < out_size; idx += N) out[idx] = 0.0f;
    }
}

extern "C" void kernel_launch(void* const* d_in, const int* in_sizes, int n_in,
                              void* d_out, int out_size)
{
    const float* lat[4]; int dims[4];
    for (int l = 0; l < 4; l++) {
        lat[l] = (const float*)d_in[l];
        dims[l] = in_sizes[l] / (2 * N);
    }
    const long long* ipA = (const long long*)d_in[4];
    const long long* ipB = (const long long*)d_in[5];
    int S0 = dims[0]/256, S1 = dims[1]/256, S2 = dims[2]/256, S3 = dims[3]/256;
    int p0 = S0, p1 = p0 + S1, p2 = p1 + S2, totSeg = p2 + S3;

    norms_all_kernel<<<dim3(2 * N, 4), 128>>>(lat[0], lat[1], lat[2], lat[3],
                                              dims[0], dims[1], dims[2], dims[3]);
    gemm_seg_kernel<<<totSeg * 9, 256>>>(lat[0], lat[1], lat[2], lat[3],
                                         dims[0], dims[1], dims[2], dims[3], p0, p1, p2);
    combine_kernel<<<(NN + 255) / 256, 256>>>(dims[0], dims[1], dims[2], dims[3]);
    lap_kernel<<<5, 32>>>();
    finalize_kernel<<<1, N>>>(ipA, ipB, (float*)d_out, out_size);
}

// round 17
// speedup vs baseline: 2.8547x; 1.3870x over previous
#include <cuda_runtime.h>
#include <stdint.h>

#define N 384
#define NN (N * N)
#define SCALE_I 16777216.0f   // 2^24: exact integer embedding of fp32 costs

__device__ float g_norms[8 * N];
__device__ float g_seg[192 * NN];    // per-256K-segment partials (64+64+32+32)
__device__ int   g_costI[5 * NN];    // int32 fixed-point costs
__device__ int   g_rowcol[5 * N];

// ---- norms: identical arithmetic to the validated R13 pipeline ----
__global__ void norms_all_kernel(const float* __restrict__ A0, const float* __restrict__ A1,
                                 const float* __restrict__ A2, const float* __restrict__ A3,
                                 int d0, int d1, int d2, int d3)
{
    int layer = blockIdx.y;
    const float* src = (layer == 0) ? A0 : (layer == 1) ? A1 : (layer == 2) ? A2 : A3;
    int d = (layer == 0) ? d0 : (layer == 1) ? d1 : (layer == 2) ? d2 : d3;
    int side = blockIdx.x / N, row = blockIdx.x - side * N;
    const float* p = src + ((size_t)side * N + row) * d;
    int t = threadIdx.x;
    float hi = 0.f, lo = 0.f; int c = 0;
    for (int k = t; k < d; k += 128, c++) {
        float x = p[k]; lo += x * x;
        if ((c & 63) == 63) { hi += lo; lo = 0.f; }
    }
    hi += lo;
    __shared__ float s[4];
    #pragma unroll
    for (int off = 16; off; off >>= 1) hi += __shfl_down_sync(0xffffffffu, hi, off);
    if ((t & 31) == 0) s[t >> 5] = hi;
    __syncthreads();
    if (t == 0) g_norms[(2 * layer + side) * N + row] = (s[0] + s[1]) + (s[2] + s[3]);
}

// ---- gemm: byte-identical to R13/R14/R16 (cost bits are frozen) ----
__global__ void __launch_bounds__(256) gemm_seg_kernel(
    const float* __restrict__ A0, const float* __restrict__ A1,
    const float* __restrict__ A2, const float* __restrict__ A3,
    int d0, int d1, int d2, int d3, int p0, int p1, int p2)
{
    int seg = blockIdx.x / 9, tile = blockIdx.x % 9;
    int layer, base;
    if (seg < p0)      { layer = 0; base = 0; }
    else if (seg < p1) { layer = 1; base = p0; }
    else if (seg < p2) { layer = 2; base = p1; }
    else               { layer = 3; base = p2; }
    const float* lat = (layer == 0) ? A0 : (layer == 1) ? A1 : (layer == 2) ? A2 : A3;
    int d = (layer == 0) ? d0 : (layer == 1) ? d1 : (layer == 2) ? d2 : d3;
    int kBase = (seg - base) * 256;
    const float* A = lat;
    const float* B = lat + (size_t)N * d;
    float* out = &g_seg[(size_t)seg * NN];

    __shared__ float As[2][8][128], Bs[2][8][128];
    int t = threadIdx.x;
    int row0 = (tile / 3) * 128, col0 = (tile % 3) * 128;
    int lrow = t >> 1, lk4 = (t & 1) * 4;
    int ty = t >> 4, tx = t & 15;

    float acc[8][8];
    #pragma unroll
    for (int i = 0; i < 8; i++)
        #pragma unroll
        for (int j = 0; j < 8; j++) acc[i][j] = 0.f;

    const float* aPtr = A + (size_t)(row0 + lrow) * d + kBase + lk4;
    const float* bPtr = B + (size_t)(col0 + lrow) * d + kBase + lk4;
    float4 pa = *(const float4*)aPtr, pb = *(const float4*)bPtr;
    As[0][lk4+0][lrow]=pa.x; As[0][lk4+1][lrow]=pa.y; As[0][lk4+2][lrow]=pa.z; As[0][lk4+3][lrow]=pa.w;
    Bs[0][lk4+0][lrow]=pb.x; Bs[0][lk4+1][lrow]=pb.y; Bs[0][lk4+2][lrow]=pb.z; Bs[0][lk4+3][lrow]=pb.w;
    __syncthreads();

    const int nPan = 32;
    for (int p = 0; p < nPan; p++) {
        int buf = p & 1;
        if (p + 1 < nPan) {
            pa = *(const float4*)(aPtr + (p + 1) * 8);
            pb = *(const float4*)(bPtr + (p + 1) * 8);
        }
        #pragma unroll
        for (int kk = 0; kk < 8; kk++) {
            float4 a0 = *(const float4*)&As[buf][kk][ty*8];
            float4 a1 = *(const float4*)&As[buf][kk][ty*8+4];
            float4 b0 = *(const float4*)&Bs[buf][kk][tx*8];
            float4 b1 = *(const float4*)&Bs[buf][kk][tx*8+4];
            float ar[8] = {a0.x,a0.y,a0.z,a0.w,a1.x,a1.y,a1.z,a1.w};
            float br[8] = {b0.x,b0.y,b0.z,b0.w,b1.x,b1.y,b1.z,b1.w};
            #pragma unroll
            for (int i = 0; i < 8; i++)
                #pragma unroll
                for (int j = 0; j < 8; j++) acc[i][j] += ar[i] * br[j];
        }
        if (p + 1 < nPan) {
            int nb = buf ^ 1;
            As[nb][lk4+0][lrow]=pa.x; As[nb][lk4+1][lrow]=pa.y; As[nb][lk4+2][lrow]=pa.z; As[nb][lk4+3][lrow]=pa.w;
            Bs[nb][lk4+0][lrow]=pb.x; Bs[nb][lk4+1][lrow]=pb.y; Bs[nb][lk4+2][lrow]=pb.z; Bs[nb][lk4+3][lrow]=pb.w;
        }
        __syncthreads();
    }
    #pragma unroll
    for (int i = 0; i < 8; i++) {
        int r = row0 + ty * 8 + i;
        float4 o0 = {acc[i][0],acc[i][1],acc[i][2],acc[i][3]};
        float4 o1 = {acc[i][4],acc[i][5],acc[i][6],acc[i][7]};
        *(float4*)&out[(size_t)r * N + col0 + tx*8]     = o0;
        *(float4*)&out[(size_t)r * N + col0 + tx*8 + 4] = o1;
    }
}

// ---- combine: byte-identical to R13/R14/R16 (cost bits frozen) ----
__global__ void combine_kernel(int d0, int d1, int d2, int d3) {
    int idx = blockIdx.x * blockDim.x + threadIdx.x;
    if (idx >= NN) return;
    int r = idx / N, c = idx % N;
    int S[4] = {d0/256, d1/256, d2/256, d3/256};
    int dd[4] = {d0, d1, d2, d3};
    const float wts[4] = {1.f, 0.5f, 0.25f, 0.125f};
    float comb = 0.f; int base = 0;
    #pragma unroll
    for (int l = 0; l < 4; l++) {
        float dot = 0.f;
        for (int sg = 0; sg < S[l]; sg++) dot += g_seg[(size_t)(base+sg)*NN + idx];
        base += S[l];
        float sq = (g_norms[2*l*N + r] - 2.0f*dot) + g_norms[(2*l+1)*N + c];
        float cost = fmaxf(sq, 0.0f) * (1.0f / (float)dd[l]);
        g_costI[(size_t)l*NN + idx] = __float2int_rn(cost * SCALE_I);
        comb = (l == 0) ? cost : comb + wts[l] * cost;
    }
    g_costI[(size_t)4*NN + idx] = __float2int_rn(comb * SCALE_I);
}

__device__ __forceinline__ unsigned long long umin64(unsigned long long a, unsigned long long b){return a<b?a:b;}

// Lexicographic warp-min of 64-bit keys via two 32-bit REDUX ops.
__device__ __forceinline__ unsigned long long warp_min_key(unsigned long long lb) {
    unsigned hi = (unsigned)(lb >> 32);
    unsigned mh = __reduce_min_sync(0xffffffffu, hi);
    unsigned lo = (hi == mh) ? (unsigned)lb : 0xffffffffu;
    unsigned ml = __reduce_min_sync(0xffffffffu, lo);
    return ((unsigned long long)mh << 32) | ml;
}

// ---- LAP: exact int64 JV, row-sequential from u=v=0 (validated order).
// key = (D<<18) | (j<<9) | (matchRow[j]+1); visited key = INF (never resurrects).
// NEW (mechanics only): during the dependent row-LDG stall, compute the
// pre-relax runner-up key (keys unique per j -> exact second-best), and
// prefetch its matched row into L1. Selection math untouched.
__global__ void __launch_bounds__(32) lap_kernel() {
    int m = blockIdx.x;
    const int* __restrict__ C = &g_costI[(size_t)m * NN];
    __shared__ long long u[N];
    __shared__ int matchRow[N], way[N];
    int lane = threadIdx.x;
    const unsigned long long INFK = ~0ull;

    long long vr[12];                 // q = s*4 + e -> col j = 128*s + 4*lane + e
    #pragma unroll
    for (int q = 0; q < 12; q++) vr[q] = 0;
    #pragma unroll
    for (int s = 0; s < 12; s++) {
        int j = lane + 32 * s;
        u[j] = 0; matchRow[j] = -1;
    }
    __syncwarp();

    for (int i = 0; i < N; i++) {
        const int4* Ci = (const int4*)(C + (size_t)i * N);
        long long D[12];
        unsigned long long key[12];
        unsigned tag[12];
        unsigned vis = 0;

        #pragma unroll
        for (int q = 0; q < 12; q++) {
            int j = 128 * (q >> 2) + 4 * lane + (q & 3);
            tag[q] = ((unsigned)j << 9) | (unsigned)(matchRow[j] + 1);
        }
        unsigned long long lb = INFK;
        #pragma unroll
        for (int s = 0; s < 3; s++) {
            int4 cc = __ldg(Ci + s * 32 + lane);
            int bj = 128 * s + 4 * lane;
            int v4[4] = {cc.x, cc.y, cc.z, cc.w};
            way[bj+0] = -1; way[bj+1] = -1; way[bj+2] = -1; way[bj+3] = -1;
            #pragma unroll
            for (int e = 0; e < 4; e++) {
                int q = s * 4 + e;
                D[q] = (long long)v4[e] - vr[q];
                key[q] = ((unsigned long long)D[q] << 18) | tag[q];
                lb = umin64(lb, key[q]);
            }
        }
        unsigned long long best = warp_min_key(lb);

        int sink = -1;
        long long mind = 0;
        for (int iter = 0; iter <= N; iter++) {
            int j1 = (int)((best >> 9) & 511);
            int i0 = (int)(best & 511) - 1;
            mind = (long long)(best >> 18);
            if (i0 < 0) { sink = j1; break; }
            int ql = ((j1 >> 7) << 2) | (j1 & 3);
            if (((j1 >> 2) & 31) == lane) { vis |= 1u << ql; key[ql] = INFK; }
            long long off = mind - u[i0];
            const int4* Cr = (const int4*)(C + (size_t)i0 * N);
            int4 c0 = __ldg(Cr + lane);
            int4 c1 = __ldg(Cr + 32 + lane);
            int4 c2 = __ldg(Cr + 64 + lane);

            // ---- speculation, entirely inside the LDG shadow ----
            // runner-up of the pre-relax key set (keys unique; winner masked)
            {
                unsigned long long lb2 = INFK;
                #pragma unroll
                for (int q = 0; q < 12; q++)
                    lb2 = umin64(lb2, (key[q] == best) ? INFK : key[q]);
                unsigned long long second = warp_min_key(lb2);
                int i0s = (int)(second & 511) - 1;
                if (i0s >= 0 && lane < 12) {
                    const int* rowp = C + (size_t)i0s * N + lane * 32;
                    asm volatile("prefetch.global.L1 [%0];" :: "l"(rowp));
                }
            }
            // -----------------------------------------------------

            int cc[12] = {c0.x, c0.y, c0.z, c0.w,
                          c1.x, c1.y, c1.z, c1.w,
                          c2.x, c2.y, c2.z, c2.w};
            lb = INFK;
            #pragma unroll
            for (int q = 0; q < 12; q++) {
                long long cand = off + (long long)cc[q] - vr[q];
                if (cand < D[q]) {
                    D[q] = cand;
                    way[128 * (q >> 2) + 4 * lane + (q & 3)] = j1;
                    key[q] = ((unsigned long long)cand << 18) | tag[q];
                }
                lb = umin64(lb, key[q]);
            }
            best = warp_min_key(lb);
        }

        #pragma unroll
        for (int q = 0; q < 12; q++) {
            if ((vis >> q) & 1) {
                int j = 128 * (q >> 2) + 4 * lane + (q & 3);
                long long dd = mind - D[q];
                vr[q] -= dd;
                u[matchRow[j]] += dd;      // distinct rows per visited col
            }
        }
        if (lane == 0) u[i] += mind;
        __syncwarp();
        if (lane == 0 && sink >= 0) {
            int jj = sink, guard = 0;
            while (guard++ <= N) {
                int pj = way[jj];
                int prev = (pj < 0) ? i : matchRow[pj];
                matchRow[jj] = prev;
                if (pj < 0) break;
                jj = pj;
            }
        }
        __syncwarp();
    }
    #pragma unroll
    for (int s = 0; s < 12; s++) {
        int j = lane + 32 * s;
        int r = matchRow[j];
        if (r >= 0) g_rowcol[m * N + r] = j;
    }
}

__global__ void finalize_kernel(const long long* __restrict__ ipA,
                                const long long* __restrict__ ipB,
                                float* __restrict__ out, int out_size)
{
    __shared__ int idealcol[N];
    __shared__ int cnt[4];
    __shared__ float s_total;
    int t = threadIdx.x;
    if (t < 4) cnt[t] = 0;
    __syncthreads();
    idealcol[(int)ipA[t]] = (int)ipB[t];
    __syncthreads();
    #pragma unroll
    for (int l = 0; l < 4; l++)
        if (g_rowcol[l * N + t] == idealcol[t]) atomicAdd(&cnt[l], 1);
    __syncthreads();
    if (t == 0) {
        const double w[4] = {1.0, 0.5, 0.25, 0.125};
        double tot = 0.0;
        for (int l = 0; l < 4; l++)
            tot += w[l] * ((double)(2 * N - 2 * cnt[l]) / (double)N);
        s_total = (float)tot;
    }
    __syncthreads();
    float total = s_total;
    int colind = g_rowcol[4 * N + t];
    if (out_size >= 2 * N + 1) {
        if (t == 0) out[0] = total;
        out[1 + t] = (float)t;
        out[1 + N + t] = (float)colind;
        for (int idx = 2 * N + 1 + t; idx < out_size; idx += N) out[idx] = 0.0f;
    } else if (out_size == 2 * N) {
        out[t] = (float)t;
        out[N + t] = (float)colind;
    } else if (out_size >= 1) {
        if (t == 0) out[0] = total;
        for (int idx = 1 + t; idx < out_size; idx += N) out[idx] = 0.0f;
    }
}

extern "C" void kernel_launch(void* const* d_in, const int* in_sizes, int n_in,
                              void* d_out, int out_size)
{
    const float* lat[4]; int dims[4];
    for (int l = 0; l < 4; l++) {
        lat[l] = (const float*)d_in[l];
        dims[l] = in_sizes[l] / (2 * N);
    }
    const long long* ipA = (const long long*)d_in[4];
    const long long* ipB = (const long long*)d_in[5];
    int S0 = dims[0]/256, S1 = dims[1]/256, S2 = dims[2]/256, S3 = dims[3]/256;
    int p0 = S0, p1 = p0 + S1, p2 = p1 + S2, totSeg = p2 + S3;

    norms_all_kernel<<<dim3(2 * N, 4), 128>>>(lat[0], lat[1], lat[2], lat[3],
                                              dims[0], dims[1], dims[2], dims[3]);
    gemm_seg_kernel<<<totSeg * 9, 256>>>(lat[0], lat[1], lat[2], lat[3],
                                         dims[0], dims[1], dims[2], dims[3], p0, p1, p2);
    combine_kernel<<<(NN + 255) / 256, 256>>>(dims[0], dims[1], dims[2], dims[3]);
    lap_kernel<<<5, 32>>>();
    finalize_kernel<<<1, N>>>(ipA, ipB, (float*)d_out, out_size);
}